// round 4
// baseline (speedup 1.0000x reference)
#include <cuda_runtime.h>
#include <cstdint>
#include <cstddef>

// out[t, n*16+f] = relu(bias[f] + sum_{j=0..31} x[t-2j-1, n] * w_pn[j][f])
// w_pn = l2-normalized relu(weights) per filter; terms with t-2j-1 < 0 are zero.
//
// Tiling: thread = 1 n-column x 2 consecutive t x all 16 f (8 packed f32x2 acc per t).
// Block = 256 threads = 8 warps: lane->n (32 cols), warp->t-pair. 64-reg cap for
// 8 warps/SMSP residency so the FFMA2 pipe (rt_SMSP=2 -> full fp32 rate) stays fed.

#define T_DIM 2048
#define N_DIM 4096
#define L_DIM 32
#define F_DIM 16
#define OUTW  (N_DIM * F_DIM)

using ull = unsigned long long;

__device__ __forceinline__ ull dup2(float v) {
    ull r;
    unsigned u = __float_as_uint(v);
    asm("mov.b64 %0, {%1, %1};" : "=l"(r) : "r"(u));
    return r;
}

__device__ __forceinline__ void fma2(ull& d, ull a, ull b) {
    asm("fma.rn.f32x2 %0, %1, %2, %0;" : "+l"(d) : "l"(a), "l"(b));
}

__device__ __forceinline__ float2 unpack2(ull v) {
    float2 r;
    asm("mov.b64 {%0, %1}, %2;" : "=f"(r.x), "=f"(r.y) : "l"(v));
    return r;
}

template<bool GUARD>
__device__ __forceinline__ float ldx(const float* __restrict__ xn, int r) {
    if (GUARD) {
        return (r >= 0) ? __ldg(xn + (size_t)r * N_DIM) : 0.0f;
    }
    return __ldg(xn + (size_t)r * N_DIM);
}

// One tile: 2 consecutive t (t0, t0+1), all 16 filters, one n column.
template<bool GUARD>
__device__ __forceinline__ void compute_tile(
    const float* __restrict__ xn,    // x + n
    float* __restrict__ outp,        // out + n*16
    const ull* __restrict__ sw8,     // smem weights as f32x2 pairs [32][8]
    const ull* __restrict__ sb2,     // smem biases  as f32x2 pairs [8]
    int t0)
{
    ull acc0[8], acc1[8];
#pragma unroll
    for (int p = 0; p < 8; ++p) {
        ull b = sb2[p];
        acc0[p] = b;
        acc1[p] = b;
    }

    // Software-pipelined x loads, depth 2.
    // Iteration j needs rows: r0 = t0-1-2j (for t0), r1 = t0-2j (for t0+1).
    float a0[2], a1[2];
    a0[0] = ldx<GUARD>(xn, t0 - 1);       // j=0
    a1[0] = ldx<GUARD>(xn, t0);
    a0[1] = ldx<GUARD>(xn, t0 - 3);       // j=1
    a1[1] = ldx<GUARD>(xn, t0 - 2);

#pragma unroll
    for (int j = 0; j < L_DIM; ++j) {
        float c0 = a0[j & 1];
        float c1 = a1[j & 1];
        if (j + 2 < L_DIM) {
            // prefetch for j+2 into the slot we just freed
            a0[j & 1] = ldx<GUARD>(xn, t0 - 1 - 2 * (j + 2));
            a1[j & 1] = ldx<GUARD>(xn, t0 - 2 * (j + 2));
        }
        ull x0 = dup2(c0);
        ull x1 = dup2(c1);
#pragma unroll
        for (int p = 0; p < 8; ++p) {
            ull wj = sw8[j * 8 + p];      // broadcast LDS.64, reused by 2 FFMA2
            fma2(acc0[p], x0, wj);
            fma2(acc1[p], x1, wj);
        }
    }

    // relu + streaming store: 16 contiguous floats per t -> 4x STG.128 each.
    // Warp lanes are consecutive n -> contiguous 2KB per row; output never
    // re-read -> .cs to keep x resident in L2.
#pragma unroll
    for (int tt = 0; tt < 2; ++tt) {
        const ull* a = tt ? acc1 : acc0;
        float4* dst = reinterpret_cast<float4*>(outp + (size_t)(t0 + tt) * OUTW);
#pragma unroll
        for (int q = 0; q < 4; ++q) {
            float2 lo = unpack2(a[2 * q]);
            float2 hi = unpack2(a[2 * q + 1]);
            float4 v;
            v.x = fmaxf(lo.x, 0.0f);
            v.y = fmaxf(lo.y, 0.0f);
            v.z = fmaxf(hi.x, 0.0f);
            v.w = fmaxf(hi.y, 0.0f);
            __stcs(dst + q, v);
        }
    }
}

__global__ void __launch_bounds__(256, 4)
tlayer_kernel(const float* __restrict__ x,
              const float* __restrict__ W,
              const float* __restrict__ B,
              float* __restrict__ out)
{
    __shared__ __align__(8) float sw[L_DIM * F_DIM];
    __shared__ __align__(8) float sb[F_DIM];

    const int tid = threadIdx.x;

    // Per-block weight prep: relu, per-filter l2-normalize (matches reference).
    if (tid < F_DIM) {
        float ss = 0.0f;
        for (int j = 0; j < L_DIM; ++j) {
            float wv = fmaxf(__ldg(W + j * F_DIM + tid), 0.0f);
            ss += wv * wv;
        }
        float inv = rsqrtf(fmaxf(ss, 1e-12f));
        for (int j = 0; j < L_DIM; ++j) {
            sw[j * F_DIM + tid] = fmaxf(__ldg(W + j * F_DIM + tid), 0.0f) * inv;
        }
        sb[tid] = __ldg(B + tid);
    }
    __syncthreads();

    const int lane = tid & 31;
    const int warp = tid >> 5;

    const int n  = blockIdx.x * 32 + lane;       // 128 n-blocks
    const int t0 = blockIdx.y * 16 + warp * 2;   // 128 t-blocks, 8 warps x 2 t

    const float* xn   = x + n;
    float*       outp = out + (size_t)n * F_DIM;
    const ull*   sw8  = reinterpret_cast<const ull*>(sw);
    const ull*   sb2  = reinterpret_cast<const ull*>(sb);

    // Deepest row touched is t0 - 63; guard only the first few t-blocks.
    if (t0 >= 63) {
        compute_tile<false>(xn, outp, sw8, sb2, t0);
    } else {
        compute_tile<true>(xn, outp, sw8, sb2, t0);
    }
}

extern "C" void kernel_launch(void* const* d_in, const int* in_sizes, int n_in,
                              void* d_out, int out_size) {
    (void)in_sizes; (void)n_in; (void)out_size;
    const float* x = (const float*)d_in[0];   // [2048, 4096]
    const float* W = (const float*)d_in[1];   // [32, 16]
    const float* B = (const float*)d_in[2];   // [16]
    float* out = (float*)d_out;               // [2048, 65536]

    dim3 grid(N_DIM / 32, T_DIM / 16);        // (128, 128)
    tlayer_kernel<<<grid, 256>>>(x, W, B, out);
}